// round 16
// baseline (speedup 1.0000x reference)
#include <cuda_runtime.h>
#include <cuda_bf16.h>
#include <cuda_fp16.h>
#include <cstdint>
#include <math.h>

#define S_TOT 16384
#define DIM   1280
#define NH    16
#define HD    80
#define NSEG  16
#define SEGL  1024
#define N_QKV (3 * DIM)
#define KDIM  1280

// ---------------- scratch (device globals; no runtime alloc) ----------------
__device__ __half g_qkv[(size_t)S_TOT * N_QKV];            // fp16 intermediate
__device__ __half g_qh[(size_t)NH * S_TOT * HD];           // [h][s][d] fp16
__device__ __half g_kh[(size_t)NH * S_TOT * HD];
__device__ __half g_vh[(size_t)DIM * S_TOT];               // [h*80+d][s] fp16
__device__ __half g_act[(size_t)S_TOT * DIM];              // fp16 activations
__device__ __half g_wq[(size_t)N_QKV * DIM];               // weights fp16
__device__ __half g_wp[(size_t)DIM * DIM];

__device__ __forceinline__ uint32_t smem_u32(const void* p) {
    uint32_t a;
    asm("{ .reg .u64 t; cvta.to.shared.u64 t, %1; cvt.u32.u64 %0, t; }" : "=r"(a) : "l"(p));
    return a;
}
__device__ __forceinline__ void ldsm4(uint32_t* f, uint32_t addr) {
    asm volatile("ldmatrix.sync.aligned.m8n8.x4.shared.b16 {%0,%1,%2,%3}, [%4];"
                 : "=r"(f[0]), "=r"(f[1]), "=r"(f[2]), "=r"(f[3]) : "r"(addr));
}
__device__ __forceinline__ void mmaf16(float* c, const uint32_t* a, const uint32_t* b) {
    asm volatile("mma.sync.aligned.m16n8k16.row.col.f32.f16.f16.f32 "
                 "{%0,%1,%2,%3},{%4,%5,%6,%7},{%8,%9},{%0,%1,%2,%3};"
                 : "+f"(c[0]), "+f"(c[1]), "+f"(c[2]), "+f"(c[3])
                 : "r"(a[0]), "r"(a[1]), "r"(a[2]), "r"(a[3]), "r"(b[0]), "r"(b[1]));
}
__device__ __forceinline__ uint32_t packh2(float x, float y) {
    __half2 v = __floats2half2_rn(x, y);
    return *(uint32_t*)&v;
}
__device__ __forceinline__ void cpa16(uint32_t s, const void* g) {
    asm volatile("cp.async.cg.shared.global [%0], [%1], 16;" :: "r"(s), "l"(g));
}
__device__ __forceinline__ void cpa_commit() {
    asm volatile("cp.async.commit_group;" ::: "memory");
}
template <int N> __device__ __forceinline__ void cpa_wait() {
    asm volatile("cp.async.wait_group %0;" :: "n"(N) : "memory");
}

// ---------------------------------------------------------------------------
// fp32 -> fp16 convert
// ---------------------------------------------------------------------------
__global__ __launch_bounds__(256)
void cvt_kernel(const float* __restrict__ src, __half* __restrict__ dst, int n4)
{
    int i = blockIdx.x * blockDim.x + threadIdx.x;
    if (i >= n4) return;
    float4 x = ((const float4*)src)[i];
    ((__half2*)dst)[2 * i]     = __floats2half2_rn(x.x, x.y);
    ((__half2*)dst)[2 * i + 1] = __floats2half2_rn(x.z, x.w);
}

// ---------------------------------------------------------------------------
// fp16 GEMM: C = A @ B^T + bias. BK=32, 4-stage cp.async, one sync per iter.
// Templated output type: __half (QKV intermediate) or float (final out).
// EXACT R13/R12 mainloop (proven fastest).
// ---------------------------------------------------------------------------
#define GTILE 10240
#define QSTG  (2 * GTILE)
#define SMEM_GEMM (4 * QSTG)        // 81920

template <typename OutT>
__global__ __launch_bounds__(256)
void gemm_f16(const __half* __restrict__ A, const __half* __restrict__ B,
              const float* __restrict__ bias, OutT* __restrict__ C, int ldc)
{
    extern __shared__ char gsm[];
    const uint32_t sb = smem_u32(gsm);

    const int t    = threadIdx.x;
    const int wid  = t >> 5;
    const int lane = t & 31;
    const int wm   = wid >> 2;
    const int wn   = wid & 3;
    const int rowBase = blockIdx.y * 128;
    const int colBase = blockIdx.x * 128;

    const uint32_t aRow = wm * 64 + (lane & 15);
    const uint32_t aKof = (lane >> 4) * 16;
    const uint32_t bRow = wn * 32 + ((lane >> 4) ? 8 : 0) + (lane & 7);
    const uint32_t bKof = ((lane >> 3) & 1) * 16;

    float acc[4][4][4] = {};

    auto issue = [&](int stage, int kt) {
        const uint32_t s0 = sb + (stage & 3) * QSTG;
#pragma unroll
        for (int j = 0; j < 2; j++) {
            const int idx = t + j * 256;
            const int r  = idx >> 2;
            const int c8 = (idx & 3) * 8;
            const size_t ga = (size_t)(rowBase + r) * KDIM + kt + c8;
            const size_t gb = (size_t)(colBase + r) * KDIM + kt + c8;
            const uint32_t so = r * 80 + c8 * 2;
            cpa16(s0 + so, A + ga);
            cpa16(s0 + GTILE + so, B + gb);
        }
        cpa_commit();
    };

    const int NT = KDIM / 32;       // 40
    issue(0, 0); issue(1, 32); issue(2, 64);

    for (int it = 0; it < NT; it++) {
        if (it + 3 <= NT)      cpa_wait<2>();
        else if (it + 2 <= NT) cpa_wait<1>();
        else                   cpa_wait<0>();
        __syncthreads();
        if (it + 3 < NT) issue(it + 3, (it + 3) * 32);

        const uint32_t s0 = sb + (it & 3) * QSTG;
#pragma unroll
        for (int ks = 0; ks < 2; ks++) {
            const uint32_t ko = ks * 32;
            uint32_t ah[4][4], bf[2][4];
#pragma unroll
            for (int mt = 0; mt < 4; mt++)
                ldsm4(ah[mt], s0 + (aRow + mt * 16) * 80 + ko + aKof);
#pragma unroll
            for (int bt = 0; bt < 2; bt++)
                ldsm4(bf[bt], s0 + GTILE + (bRow + bt * 16) * 80 + ko + bKof);
#pragma unroll
            for (int mt = 0; mt < 4; mt++)
#pragma unroll
                for (int nt = 0; nt < 4; nt++)
                    mmaf16(acc[mt][nt], ah[mt], &bf[nt >> 1][(nt & 1) * 2]);
        }
    }

    const int g   = lane >> 2;
    const int tig = lane & 3;
#pragma unroll
    for (int mt = 0; mt < 4; mt++) {
        const int r0 = rowBase + wm * 64 + mt * 16 + g;
#pragma unroll
        for (int nt = 0; nt < 4; nt++) {
            const int col = colBase + wn * 32 + nt * 8 + tig * 2;
            const float b0 = bias[col], b1 = bias[col + 1];
            const float v00 = acc[mt][nt][0] + b0, v01 = acc[mt][nt][1] + b1;
            const float v10 = acc[mt][nt][2] + b0, v11 = acc[mt][nt][3] + b1;
            if constexpr (sizeof(OutT) == 2) {
                *(uint32_t*)((__half*)C + (size_t)r0 * ldc + col)       = packh2(v00, v01);
                *(uint32_t*)((__half*)C + (size_t)(r0 + 8) * ldc + col) = packh2(v10, v11);
            } else {
                *(float2*)((float*)C + (size_t)r0 * ldc + col)       = make_float2(v00, v01);
                *(float2*)((float*)C + (size_t)(r0 + 8) * ldc + col) = make_float2(v10, v11);
            }
        }
    }
}

// ---------------------------------------------------------------------------
// RoPE + scatter: g_qkv (fp16) -> fp16 q/k [h][s][d] (+ q scaling)
// ---------------------------------------------------------------------------
__global__ __launch_bounds__(256)
void rope_scatter(const float* __restrict__ cosb, const float* __restrict__ sinb)
{
    const int idx = blockIdx.x * blockDim.x + threadIdx.x;
    const int total = NH * S_TOT * (HD / 2);
    if (idx >= total) return;
    const int d    = idx % (HD / 2);
    const int rest = idx / (HD / 2);
    const int s = rest % S_TOT;
    const int h = rest / S_TOT;

    const float c0 = cosb[s * HD + d];
    const float c1 = cosb[s * HD + d + 40];
    const float s0 = sinb[s * HD + d];
    const float s1 = sinb[s * HD + d + 40];

    const size_t src  = (size_t)s * N_QKV + h * HD + d;
    const size_t dstb = ((size_t)h * S_TOT + s) * HD + d;
    const float scale = 0.11180339887498948f;

    float q0 = __half2float(g_qkv[src]);
    float q1 = __half2float(g_qkv[src + 40]);
    float k0 = __half2float(g_qkv[src + DIM]);
    float k1 = __half2float(g_qkv[src + DIM + 40]);

    g_qh[dstb]      = __float2half((q0 * c0 - q1 * s0) * scale);
    g_qh[dstb + 40] = __float2half((q1 * c1 + q0 * s1) * scale);
    g_kh[dstb]      = __float2half(k0 * c0 - k1 * s0);
    g_kh[dstb + 40] = __float2half(k1 * c1 + k0 * s1);
}

// ---------------------------------------------------------------------------
// V: transpose fp16  g_qkv[s][2*DIM + hd] -> g_vh[hd][s]
// ---------------------------------------------------------------------------
__global__ __launch_bounds__(256)
void v_split_t()
{
    __shared__ __half tile[32][40];     // pad 40 halves: conflict-free columns
    const int t = threadIdx.x;
    const int sBase  = blockIdx.x * 32;
    const int hdBase = blockIdx.y * 32;

    const int tx = t & 31, ty = t >> 5;
#pragma unroll
    for (int j = 0; j < 4; j++) {
        const int r = ty + j * 8;
        tile[r][tx] = g_qkv[(size_t)(sBase + r) * N_QKV + 2 * DIM + hdBase + tx];
    }
    __syncthreads();

    const int r2 = t >> 3;
    const int sp = (t & 7) * 4;
    __half2 a01 = __half2(tile[sp + 0][r2], tile[sp + 1][r2]);
    __half2 a23 = __half2(tile[sp + 2][r2], tile[sp + 3][r2]);
    const size_t o = (size_t)(hdBase + r2) * S_TOT + sBase + sp;
    *(__half2*)(g_vh + o)     = a01;
    *(__half2*)(g_vh + o + 2) = a23;
}

// ---------------------------------------------------------------------------
// fp16 tensor-core flash attention — EXACT R13 version.
// ---------------------------------------------------------------------------
#define AQ    0
#define AK0   22528
#define AKSZ  22528
#define AV0   67584
#define AVSZ  21760
#define ATTN_SMEM 111104

__global__ __launch_bounds__(256, 2)
void attn_mma()
{
    extern __shared__ char sm[];
    const uint32_t sb = smem_u32(sm);
    const int t    = threadIdx.x;
    const int wid  = t >> 5;
    const int lane = t & 31;
    const int qb = blockIdx.x, h = blockIdx.y, seg = blockIdx.z;
    const int segBase = seg * SEGL;
    const int s0 = segBase + qb * 128;

    {
        const size_t qBase = ((size_t)h * S_TOT + s0) * HD;
#pragma unroll
        for (int j = 0; j < 5; j++) {
            const int idx = t + j * 256;
            const int r  = idx / 10;
            const int c8 = (idx % 10) * 8;
            *(uint4*)(sm + AQ + r * 176 + c8 * 2) =
                *(const uint4*)(g_qh + qBase + (size_t)r * HD + c8);
        }
    }

    auto issueKV = [&](int stage, int kc) {
        const uint32_t kb = sb + AK0 + stage * AKSZ;
        const uint32_t vb = sb + AV0 + stage * AVSZ;
#pragma unroll
        for (int j = 0; j < 5; j++) {
            const int idx = t + j * 256;
            const int r  = idx / 10;
            const int c8 = (idx % 10) * 8;
            cpa16(kb + r * 176 + c8 * 2,
                  g_kh + ((size_t)h * S_TOT + segBase + kc + r) * HD + c8);
        }
#pragma unroll
        for (int j = 0; j < 5; j++) {
            const int idx = t + j * 256;
            const int r  = idx >> 4;
            const int c8 = (idx & 15) * 8;
            cpa16(vb + r * 272 + c8 * 2,
                  g_vh + ((size_t)(h * HD + r)) * S_TOT + segBase + kc + c8);
        }
        cpa_commit();
    };

    const uint32_t aRowOff = (wid * 16 + (lane & 15));
    const uint32_t aKof = (lane >> 4) * 16;
    const uint32_t bRowSub = ((lane >> 4) ? 8 : 0) + (lane & 7);
    const uint32_t bKof = ((lane >> 3) & 1) * 16;

    const int g   = lane >> 2;
    const int tig = lane & 3;

    float m0 = -1e30f, m1 = -1e30f, l0 = 0.f, l1 = 0.f;
    float oacc[10][4] = {};

    issueKV(0, 0);
    for (int it = 0; it < 8; it++) {
        if (it < 7) { issueKV((it + 1) & 1, (it + 1) * 128); cpa_wait<1>(); }
        else        { cpa_wait<0>(); }
        __syncthreads();

        const uint32_t kS = sb + AK0 + (it & 1) * AKSZ;
        const uint32_t vS = sb + AV0 + (it & 1) * AVSZ;

        float acc[16][4];
#pragma unroll
        for (int nt = 0; nt < 16; nt++)
#pragma unroll
            for (int c = 0; c < 4; c++) acc[nt][c] = 0.f;

#pragma unroll
        for (int ks = 0; ks < 5; ks++) {
            const uint32_t ko = ks * 32;
            uint32_t qf[4];
            ldsm4(qf, sb + AQ + aRowOff * 176 + ko + aKof);
#pragma unroll
            for (int bp = 0; bp < 4; bp++) {
                uint32_t k0f[4], k1f[4];
                ldsm4(k0f, kS + ((2 * bp) * 16 + bRowSub) * 176 + ko + bKof);
                ldsm4(k1f, kS + ((2 * bp + 1) * 16 + bRowSub) * 176 + ko + bKof);
                mmaf16(acc[4 * bp + 0], qf, k0f + 0);
                mmaf16(acc[4 * bp + 1], qf, k0f + 2);
                mmaf16(acc[4 * bp + 2], qf, k1f + 0);
                mmaf16(acc[4 * bp + 3], qf, k1f + 2);
            }
        }

        float mx0 = -1e30f, mx1 = -1e30f;
#pragma unroll
        for (int nt = 0; nt < 16; nt++) {
            mx0 = fmaxf(mx0, fmaxf(acc[nt][0], acc[nt][1]));
            mx1 = fmaxf(mx1, fmaxf(acc[nt][2], acc[nt][3]));
        }
        mx0 = fmaxf(mx0, __shfl_xor_sync(0xffffffffu, mx0, 1));
        mx0 = fmaxf(mx0, __shfl_xor_sync(0xffffffffu, mx0, 2));
        mx1 = fmaxf(mx1, __shfl_xor_sync(0xffffffffu, mx1, 1));
        mx1 = fmaxf(mx1, __shfl_xor_sync(0xffffffffu, mx1, 2));

        const float mn0 = fmaxf(m0, mx0);
        const float mn1 = fmaxf(m1, mx1);
        const float cr0 = __expf(m0 - mn0);
        const float cr1 = __expf(m1 - mn1);
        m0 = mn0; m1 = mn1;

        float rs0 = 0.f, rs1 = 0.f;
#pragma unroll
        for (int nt = 0; nt < 16; nt++) {
            acc[nt][0] = __expf(acc[nt][0] - mn0);
            acc[nt][1] = __expf(acc[nt][1] - mn0);
            acc[nt][2] = __expf(acc[nt][2] - mn1);
            acc[nt][3] = __expf(acc[nt][3] - mn1);
            rs0 += acc[nt][0] + acc[nt][1];
            rs1 += acc[nt][2] + acc[nt][3];
        }
        rs0 += __shfl_xor_sync(0xffffffffu, rs0, 1);
        rs0 += __shfl_xor_sync(0xffffffffu, rs0, 2);
        rs1 += __shfl_xor_sync(0xffffffffu, rs1, 1);
        rs1 += __shfl_xor_sync(0xffffffffu, rs1, 2);
        l0 = l0 * cr0 + rs0;
        l1 = l1 * cr1 + rs1;

#pragma unroll
        for (int vt = 0; vt < 10; vt++) {
            oacc[vt][0] *= cr0; oacc[vt][1] *= cr0;
            oacc[vt][2] *= cr1; oacc[vt][3] *= cr1;
        }

#pragma unroll
        for (int ks = 0; ks < 8; ks++) {
            uint32_t pf[4];
            pf[0] = packh2(acc[2 * ks][0],     acc[2 * ks][1]);
            pf[1] = packh2(acc[2 * ks][2],     acc[2 * ks][3]);
            pf[2] = packh2(acc[2 * ks + 1][0], acc[2 * ks + 1][1]);
            pf[3] = packh2(acc[2 * ks + 1][2], acc[2 * ks + 1][3]);
            const uint32_t ko = ks * 32;
#pragma unroll
            for (int bt = 0; bt < 5; bt++) {
                uint32_t vf[4];
                ldsm4(vf, vS + (bt * 16 + bRowSub) * 272 + ko + bKof);
                mmaf16(oacc[2 * bt],     pf, vf + 0);
                mmaf16(oacc[2 * bt + 1], pf, vf + 2);
            }
        }
        __syncthreads();
    }

    const float inv0 = 1.0f / l0;
    const float inv1 = 1.0f / l1;
    const int srow0 = s0 + wid * 16 + g;
    const int srow1 = srow0 + 8;
#pragma unroll
    for (int vt = 0; vt < 10; vt++) {
        const int col = h * HD + vt * 8 + tig * 2;
        *(uint32_t*)(g_act + (size_t)srow0 * DIM + col) =
            packh2(oacc[vt][0] * inv0, oacc[vt][1] * inv0);
        *(uint32_t*)(g_act + (size_t)srow1 * DIM + col) =
            packh2(oacc[vt][2] * inv1, oacc[vt][3] * inv1);
    }
}

// ---------------------------------------------------------------------------
extern "C" void kernel_launch(void* const* d_in, const int* in_sizes, int n_in,
                              void* d_out, int out_size)
{
    const float* hidden = (const float*)d_in[0];
    const float* cosb   = (const float*)d_in[2];
    const float* sinb   = (const float*)d_in[3];
    const float* qkv_w  = (const float*)d_in[4];
    const float* qkv_b  = (const float*)d_in[5];
    const float* proj_w = (const float*)d_in[6];
    const float* proj_b = (const float*)d_in[7];
    float* out = (float*)d_out;

    __half *p_qkv, *p_act, *p_wq, *p_wp;
    cudaGetSymbolAddress((void**)&p_qkv, g_qkv);
    cudaGetSymbolAddress((void**)&p_act, g_act);
    cudaGetSymbolAddress((void**)&p_wq,  g_wq);
    cudaGetSymbolAddress((void**)&p_wp,  g_wp);

    cudaFuncSetAttribute(attn_mma,
                         cudaFuncAttributeMaxDynamicSharedMemorySize, ATTN_SMEM);
    cudaFuncSetAttribute(gemm_f16<__half>,
                         cudaFuncAttributeMaxDynamicSharedMemorySize, SMEM_GEMM);
    cudaFuncSetAttribute(gemm_f16<float>,
                         cudaFuncAttributeMaxDynamicSharedMemorySize, SMEM_GEMM);

    // 1) convert hidden + weights to fp16
    {
        int n4 = S_TOT * DIM / 4;
        cvt_kernel<<<(n4 + 255) / 256, 256>>>(hidden, p_act, n4);
        n4 = N_QKV * DIM / 4;
        cvt_kernel<<<(n4 + 255) / 256, 256>>>(qkv_w, p_wq, n4);
        n4 = DIM * DIM / 4;
        cvt_kernel<<<(n4 + 255) / 256, 256>>>(proj_w, p_wp, n4);
    }

    // 2) QKV GEMM -> fp16 intermediate
    gemm_f16<__half><<<dim3(N_QKV / 128, S_TOT / 128), 256, SMEM_GEMM>>>(
        p_act, p_wq, qkv_b, p_qkv, N_QKV);

    // 3) RoPE + V transpose (fp16 reads)
    {
        const int total = NH * S_TOT * (HD / 2);
        rope_scatter<<<(total + 255) / 256, 256>>>(cosb, sinb);
        v_split_t<<<dim3(S_TOT / 32, DIM / 32), 256>>>();
    }

    // 4) attention -> fp16 activations
    attn_mma<<<dim3(SEGL / 128, NH, NSEG), 256, ATTN_SMEM>>>();

    // 5) output projection -> fp32 out
    gemm_f16<float><<<dim3(DIM / 128, S_TOT / 128), 256, SMEM_GEMM>>>(
        p_act, p_wp, proj_b, out, DIM);
}

// round 17
// speedup vs baseline: 1.5124x; 1.5124x over previous
#include <cuda_runtime.h>
#include <cuda_bf16.h>
#include <cuda_fp16.h>
#include <cstdint>
#include <math.h>

#define S_TOT 16384
#define DIM   1280
#define NH    16
#define HD    80
#define NSEG  16
#define SEGL  1024
#define N_QKV (3 * DIM)
#define KDIM  1280

// ---------------- scratch (device globals; no runtime alloc) ----------------
__device__ float g_qkv[(size_t)S_TOT * N_QKV];
__device__ __half g_qh[(size_t)NH * S_TOT * HD];           // [h][s][d] fp16
__device__ __half g_kh[(size_t)NH * S_TOT * HD];
__device__ __half g_vh[(size_t)DIM * S_TOT];               // [h*80+d][s] fp16
__device__ __half g_act[(size_t)S_TOT * DIM];              // fp16 activations
__device__ __half g_wq[(size_t)N_QKV * DIM];               // weights fp16
__device__ __half g_wp[(size_t)DIM * DIM];

__device__ __forceinline__ uint32_t smem_u32(const void* p) {
    uint32_t a;
    asm("{ .reg .u64 t; cvta.to.shared.u64 t, %1; cvt.u32.u64 %0, t; }" : "=r"(a) : "l"(p));
    return a;
}
__device__ __forceinline__ void ldsm4(uint32_t* f, uint32_t addr) {
    asm volatile("ldmatrix.sync.aligned.m8n8.x4.shared.b16 {%0,%1,%2,%3}, [%4];"
                 : "=r"(f[0]), "=r"(f[1]), "=r"(f[2]), "=r"(f[3]) : "r"(addr));
}
__device__ __forceinline__ void mmaf16(float* c, const uint32_t* a, const uint32_t* b) {
    asm volatile("mma.sync.aligned.m16n8k16.row.col.f32.f16.f16.f32 "
                 "{%0,%1,%2,%3},{%4,%5,%6,%7},{%8,%9},{%0,%1,%2,%3};"
                 : "+f"(c[0]), "+f"(c[1]), "+f"(c[2]), "+f"(c[3])
                 : "r"(a[0]), "r"(a[1]), "r"(a[2]), "r"(a[3]), "r"(b[0]), "r"(b[1]));
}
__device__ __forceinline__ uint32_t packh2(float x, float y) {
    __half2 v = __floats2half2_rn(x, y);
    return *(uint32_t*)&v;
}
__device__ __forceinline__ void cpa16(uint32_t s, const void* g) {
    asm volatile("cp.async.cg.shared.global [%0], [%1], 16;" :: "r"(s), "l"(g));
}
__device__ __forceinline__ void cpa_commit() {
    asm volatile("cp.async.commit_group;" ::: "memory");
}
template <int N> __device__ __forceinline__ void cpa_wait() {
    asm volatile("cp.async.wait_group %0;" :: "n"(N) : "memory");
}

// ---------------------------------------------------------------------------
// fp32 -> fp16 convert
// ---------------------------------------------------------------------------
__global__ __launch_bounds__(256)
void cvt_kernel(const float* __restrict__ src, __half* __restrict__ dst, int n4)
{
    int i = blockIdx.x * blockDim.x + threadIdx.x;
    if (i >= n4) return;
    float4 x = ((const float4*)src)[i];
    ((__half2*)dst)[2 * i]     = __floats2half2_rn(x.x, x.y);
    ((__half2*)dst)[2 * i + 1] = __floats2half2_rn(x.z, x.w);
}

// ---------------------------------------------------------------------------
// fp16 GEMM: C = A @ B^T + bias. BK=32, 4-stage cp.async, one sync per iter.
// EXACT R13/R12 version (proven fastest: fp32 output, full-sector stores).
// ---------------------------------------------------------------------------
#define GTILE 10240
#define QSTG  (2 * GTILE)
#define SMEM_GEMM (4 * QSTG)        // 81920

__global__ __launch_bounds__(256)
void gemm_f16(const __half* __restrict__ A, const __half* __restrict__ B,
              const float* __restrict__ bias, float* __restrict__ C, int ldc)
{
    extern __shared__ char gsm[];
    const uint32_t sb = smem_u32(gsm);

    const int t    = threadIdx.x;
    const int wid  = t >> 5;
    const int lane = t & 31;
    const int wm   = wid >> 2;
    const int wn   = wid & 3;
    const int rowBase = blockIdx.y * 128;
    const int colBase = blockIdx.x * 128;

    const uint32_t aRow = wm * 64 + (lane & 15);
    const uint32_t aKof = (lane >> 4) * 16;
    const uint32_t bRow = wn * 32 + ((lane >> 4) ? 8 : 0) + (lane & 7);
    const uint32_t bKof = ((lane >> 3) & 1) * 16;

    float acc[4][4][4] = {};

    auto issue = [&](int stage, int kt) {
        const uint32_t s0 = sb + (stage & 3) * QSTG;
#pragma unroll
        for (int j = 0; j < 2; j++) {
            const int idx = t + j * 256;
            const int r  = idx >> 2;
            const int c8 = (idx & 3) * 8;
            const size_t ga = (size_t)(rowBase + r) * KDIM + kt + c8;
            const size_t gb = (size_t)(colBase + r) * KDIM + kt + c8;
            const uint32_t so = r * 80 + c8 * 2;
            cpa16(s0 + so, A + ga);
            cpa16(s0 + GTILE + so, B + gb);
        }
        cpa_commit();
    };

    const int NT = KDIM / 32;       // 40
    issue(0, 0); issue(1, 32); issue(2, 64);

    for (int it = 0; it < NT; it++) {
        if (it + 3 <= NT)      cpa_wait<2>();
        else if (it + 2 <= NT) cpa_wait<1>();
        else                   cpa_wait<0>();
        __syncthreads();
        if (it + 3 < NT) issue(it + 3, (it + 3) * 32);

        const uint32_t s0 = sb + (it & 3) * QSTG;
#pragma unroll
        for (int ks = 0; ks < 2; ks++) {
            const uint32_t ko = ks * 32;
            uint32_t ah[4][4], bf[2][4];
#pragma unroll
            for (int mt = 0; mt < 4; mt++)
                ldsm4(ah[mt], s0 + (aRow + mt * 16) * 80 + ko + aKof);
#pragma unroll
            for (int bt = 0; bt < 2; bt++)
                ldsm4(bf[bt], s0 + GTILE + (bRow + bt * 16) * 80 + ko + bKof);
#pragma unroll
            for (int mt = 0; mt < 4; mt++)
#pragma unroll
                for (int nt = 0; nt < 4; nt++)
                    mmaf16(acc[mt][nt], ah[mt], &bf[nt >> 1][(nt & 1) * 2]);
        }
    }

    const int g   = lane >> 2;
    const int tig = lane & 3;
#pragma unroll
    for (int mt = 0; mt < 4; mt++) {
        const int r0 = rowBase + wm * 64 + mt * 16 + g;
#pragma unroll
        for (int nt = 0; nt < 4; nt++) {
            const int col = colBase + wn * 32 + nt * 8 + tig * 2;
            const float b0 = bias[col], b1 = bias[col + 1];
            float2 o0 = make_float2(acc[mt][nt][0] + b0, acc[mt][nt][1] + b1);
            float2 o1 = make_float2(acc[mt][nt][2] + b0, acc[mt][nt][3] + b1);
            *(float2*)(C + (size_t)r0 * ldc + col)       = o0;
            *(float2*)(C + (size_t)(r0 + 8) * ldc + col) = o1;
        }
    }
}

// ---------------------------------------------------------------------------
// RoPE + scatter, 2-wide vectorized: each thread handles d, d+1 (and +40 pair)
// ---------------------------------------------------------------------------
__global__ __launch_bounds__(256)
void rope_scatter(const float* __restrict__ cosb, const float* __restrict__ sinb)
{
    const int idx = blockIdx.x * blockDim.x + threadIdx.x;
    const int total = NH * S_TOT * (HD / 4);    // 20 d-pairs per (h,s)
    if (idx >= total) return;
    const int d2   = idx % (HD / 4);
    const int rest = idx / (HD / 4);
    const int s = rest % S_TOT;
    const int h = rest / S_TOT;
    const int d = d2 * 2;

    const float2 c0 = *(const float2*)(cosb + s * HD + d);
    const float2 c1 = *(const float2*)(cosb + s * HD + d + 40);
    const float2 s0 = *(const float2*)(sinb + s * HD + d);
    const float2 s1 = *(const float2*)(sinb + s * HD + d + 40);

    const size_t src  = (size_t)s * N_QKV + h * HD + d;
    const size_t dstb = ((size_t)h * S_TOT + s) * HD + d;
    const float scale = 0.11180339887498948f;

    const float2 q0 = *(const float2*)(g_qkv + src);
    const float2 q1 = *(const float2*)(g_qkv + src + 40);
    const float2 k0 = *(const float2*)(g_qkv + src + DIM);
    const float2 k1 = *(const float2*)(g_qkv + src + DIM + 40);

    *(__half2*)(g_qh + dstb) = __floats2half2_rn(
        (q0.x * c0.x - q1.x * s0.x) * scale, (q0.y * c0.y - q1.y * s0.y) * scale);
    *(__half2*)(g_qh + dstb + 40) = __floats2half2_rn(
        (q1.x * c1.x + q0.x * s1.x) * scale, (q1.y * c1.y + q0.y * s1.y) * scale);
    *(__half2*)(g_kh + dstb) = __floats2half2_rn(
        k0.x * c0.x - k1.x * s0.x, k0.y * c0.y - k1.y * s0.y);
    *(__half2*)(g_kh + dstb + 40) = __floats2half2_rn(
        k1.x * c1.x + k0.x * s1.x, k1.y * c1.y + k0.y * s1.y);
}

// ---------------------------------------------------------------------------
// V: transpose to fp16  g_qkv[s][2*DIM + hd] -> g_vh[hd][s]  (EXACT R13)
// ---------------------------------------------------------------------------
__global__ __launch_bounds__(256)
void v_split_t()
{
    __shared__ float tile[32][33];
    const int t = threadIdx.x;
    const int sBase  = blockIdx.x * 32;
    const int hdBase = blockIdx.y * 32;

    const int tx = t & 31, ty = t >> 5;
#pragma unroll
    for (int j = 0; j < 4; j++) {
        const int r = ty + j * 8;
        tile[r][tx] = g_qkv[(size_t)(sBase + r) * N_QKV + 2 * DIM + hdBase + tx];
    }
    __syncthreads();

    const int r2 = t >> 3;
    const int sp = (t & 7) * 4;
    __half2 a01 = __floats2half2_rn(tile[sp + 0][r2], tile[sp + 1][r2]);
    __half2 a23 = __floats2half2_rn(tile[sp + 2][r2], tile[sp + 3][r2]);
    const size_t o = (size_t)(hdBase + r2) * S_TOT + sBase + sp;
    *(__half2*)(g_vh + o)     = a01;
    *(__half2*)(g_vh + o + 2) = a23;
}

// ---------------------------------------------------------------------------
// fp16 tensor-core flash attention — EXACT R13 version.
// ---------------------------------------------------------------------------
#define AQ    0
#define AK0   22528
#define AKSZ  22528
#define AV0   67584
#define AVSZ  21760
#define ATTN_SMEM 111104

__global__ __launch_bounds__(256, 2)
void attn_mma()
{
    extern __shared__ char sm[];
    const uint32_t sb = smem_u32(sm);
    const int t    = threadIdx.x;
    const int wid  = t >> 5;
    const int lane = t & 31;
    const int qb = blockIdx.x, h = blockIdx.y, seg = blockIdx.z;
    const int segBase = seg * SEGL;
    const int s0 = segBase + qb * 128;

    {
        const size_t qBase = ((size_t)h * S_TOT + s0) * HD;
#pragma unroll
        for (int j = 0; j < 5; j++) {
            const int idx = t + j * 256;
            const int r  = idx / 10;
            const int c8 = (idx % 10) * 8;
            *(uint4*)(sm + AQ + r * 176 + c8 * 2) =
                *(const uint4*)(g_qh + qBase + (size_t)r * HD + c8);
        }
    }

    auto issueKV = [&](int stage, int kc) {
        const uint32_t kb = sb + AK0 + stage * AKSZ;
        const uint32_t vb = sb + AV0 + stage * AVSZ;
#pragma unroll
        for (int j = 0; j < 5; j++) {
            const int idx = t + j * 256;
            const int r  = idx / 10;
            const int c8 = (idx % 10) * 8;
            cpa16(kb + r * 176 + c8 * 2,
                  g_kh + ((size_t)h * S_TOT + segBase + kc + r) * HD + c8);
        }
#pragma unroll
        for (int j = 0; j < 5; j++) {
            const int idx = t + j * 256;
            const int r  = idx >> 4;
            const int c8 = (idx & 15) * 8;
            cpa16(vb + r * 272 + c8 * 2,
                  g_vh + ((size_t)(h * HD + r)) * S_TOT + segBase + kc + c8);
        }
        cpa_commit();
    };

    const uint32_t aRowOff = (wid * 16 + (lane & 15));
    const uint32_t aKof = (lane >> 4) * 16;
    const uint32_t bRowSub = ((lane >> 4) ? 8 : 0) + (lane & 7);
    const uint32_t bKof = ((lane >> 3) & 1) * 16;

    const int g   = lane >> 2;
    const int tig = lane & 3;

    float m0 = -1e30f, m1 = -1e30f, l0 = 0.f, l1 = 0.f;
    float oacc[10][4] = {};

    issueKV(0, 0);
    for (int it = 0; it < 8; it++) {
        if (it < 7) { issueKV((it + 1) & 1, (it + 1) * 128); cpa_wait<1>(); }
        else        { cpa_wait<0>(); }
        __syncthreads();

        const uint32_t kS = sb + AK0 + (it & 1) * AKSZ;
        const uint32_t vS = sb + AV0 + (it & 1) * AVSZ;

        float acc[16][4];
#pragma unroll
        for (int nt = 0; nt < 16; nt++)
#pragma unroll
            for (int c = 0; c < 4; c++) acc[nt][c] = 0.f;

#pragma unroll
        for (int ks = 0; ks < 5; ks++) {
            const uint32_t ko = ks * 32;
            uint32_t qf[4];
            ldsm4(qf, sb + AQ + aRowOff * 176 + ko + aKof);
#pragma unroll
            for (int bp = 0; bp < 4; bp++) {
                uint32_t k0f[4], k1f[4];
                ldsm4(k0f, kS + ((2 * bp) * 16 + bRowSub) * 176 + ko + bKof);
                ldsm4(k1f, kS + ((2 * bp + 1) * 16 + bRowSub) * 176 + ko + bKof);
                mmaf16(acc[4 * bp + 0], qf, k0f + 0);
                mmaf16(acc[4 * bp + 1], qf, k0f + 2);
                mmaf16(acc[4 * bp + 2], qf, k1f + 0);
                mmaf16(acc[4 * bp + 3], qf, k1f + 2);
            }
        }

        float mx0 = -1e30f, mx1 = -1e30f;
#pragma unroll
        for (int nt = 0; nt < 16; nt++) {
            mx0 = fmaxf(mx0, fmaxf(acc[nt][0], acc[nt][1]));
            mx1 = fmaxf(mx1, fmaxf(acc[nt][2], acc[nt][3]));
        }
        mx0 = fmaxf(mx0, __shfl_xor_sync(0xffffffffu, mx0, 1));
        mx0 = fmaxf(mx0, __shfl_xor_sync(0xffffffffu, mx0, 2));
        mx1 = fmaxf(mx1, __shfl_xor_sync(0xffffffffu, mx1, 1));
        mx1 = fmaxf(mx1, __shfl_xor_sync(0xffffffffu, mx1, 2));

        const float mn0 = fmaxf(m0, mx0);
        const float mn1 = fmaxf(m1, mx1);
        const float cr0 = __expf(m0 - mn0);
        const float cr1 = __expf(m1 - mn1);
        m0 = mn0; m1 = mn1;

        float rs0 = 0.f, rs1 = 0.f;
#pragma unroll
        for (int nt = 0; nt < 16; nt++) {
            acc[nt][0] = __expf(acc[nt][0] - mn0);
            acc[nt][1] = __expf(acc[nt][1] - mn0);
            acc[nt][2] = __expf(acc[nt][2] - mn1);
            acc[nt][3] = __expf(acc[nt][3] - mn1);
            rs0 += acc[nt][0] + acc[nt][1];
            rs1 += acc[nt][2] + acc[nt][3];
        }
        rs0 += __shfl_xor_sync(0xffffffffu, rs0, 1);
        rs0 += __shfl_xor_sync(0xffffffffu, rs0, 2);
        rs1 += __shfl_xor_sync(0xffffffffu, rs1, 1);
        rs1 += __shfl_xor_sync(0xffffffffu, rs1, 2);
        l0 = l0 * cr0 + rs0;
        l1 = l1 * cr1 + rs1;

#pragma unroll
        for (int vt = 0; vt < 10; vt++) {
            oacc[vt][0] *= cr0; oacc[vt][1] *= cr0;
            oacc[vt][2] *= cr1; oacc[vt][3] *= cr1;
        }

#pragma unroll
        for (int ks = 0; ks < 8; ks++) {
            uint32_t pf[4];
            pf[0] = packh2(acc[2 * ks][0],     acc[2 * ks][1]);
            pf[1] = packh2(acc[2 * ks][2],     acc[2 * ks][3]);
            pf[2] = packh2(acc[2 * ks + 1][0], acc[2 * ks + 1][1]);
            pf[3] = packh2(acc[2 * ks + 1][2], acc[2 * ks + 1][3]);
            const uint32_t ko = ks * 32;
#pragma unroll
            for (int bt = 0; bt < 5; bt++) {
                uint32_t vf[4];
                ldsm4(vf, vS + (bt * 16 + bRowSub) * 272 + ko + bKof);
                mmaf16(oacc[2 * bt],     pf, vf + 0);
                mmaf16(oacc[2 * bt + 1], pf, vf + 2);
            }
        }
        __syncthreads();
    }

    const float inv0 = 1.0f / l0;
    const float inv1 = 1.0f / l1;
    const int srow0 = s0 + wid * 16 + g;
    const int srow1 = srow0 + 8;
#pragma unroll
    for (int vt = 0; vt < 10; vt++) {
        const int col = h * HD + vt * 8 + tig * 2;
        *(uint32_t*)(g_act + (size_t)srow0 * DIM + col) =
            packh2(oacc[vt][0] * inv0, oacc[vt][1] * inv0);
        *(uint32_t*)(g_act + (size_t)srow1 * DIM + col) =
            packh2(oacc[vt][2] * inv1, oacc[vt][3] * inv1);
    }
}

// ---------------------------------------------------------------------------
extern "C" void kernel_launch(void* const* d_in, const int* in_sizes, int n_in,
                              void* d_out, int out_size)
{
    const float* hidden = (const float*)d_in[0];
    const float* cosb   = (const float*)d_in[2];
    const float* sinb   = (const float*)d_in[3];
    const float* qkv_w  = (const float*)d_in[4];
    const float* qkv_b  = (const float*)d_in[5];
    const float* proj_w = (const float*)d_in[6];
    const float* proj_b = (const float*)d_in[7];
    float* out = (float*)d_out;

    float* p_qkv;
    __half *p_act, *p_wq, *p_wp;
    cudaGetSymbolAddress((void**)&p_qkv, g_qkv);
    cudaGetSymbolAddress((void**)&p_act, g_act);
    cudaGetSymbolAddress((void**)&p_wq,  g_wq);
    cudaGetSymbolAddress((void**)&p_wp,  g_wp);

    cudaFuncSetAttribute(attn_mma,
                         cudaFuncAttributeMaxDynamicSharedMemorySize, ATTN_SMEM);
    cudaFuncSetAttribute(gemm_f16,
                         cudaFuncAttributeMaxDynamicSharedMemorySize, SMEM_GEMM);

    // 1) convert hidden + weights to fp16
    {
        int n4 = S_TOT * DIM / 4;
        cvt_kernel<<<(n4 + 255) / 256, 256>>>(hidden, p_act, n4);
        n4 = N_QKV * DIM / 4;
        cvt_kernel<<<(n4 + 255) / 256, 256>>>(qkv_w, p_wq, n4);
        n4 = DIM * DIM / 4;
        cvt_kernel<<<(n4 + 255) / 256, 256>>>(proj_w, p_wp, n4);
    }

    // 2) QKV GEMM (fp32 intermediate — full-sector stores)
    gemm_f16<<<dim3(N_QKV / 128, S_TOT / 128), 256, SMEM_GEMM>>>(
        p_act, p_wq, qkv_b, p_qkv, N_QKV);

    // 3) RoPE (vectorized) + V transpose
    {
        const int total = NH * S_TOT * (HD / 4);
        rope_scatter<<<(total + 255) / 256, 256>>>(cosb, sinb);
        v_split_t<<<dim3(S_TOT / 32, DIM / 32), 256>>>();
    }

    // 4) attention -> fp16 activations
    attn_mma<<<dim3(SEGL / 128, NH, NSEG), 256, ATTN_SMEM>>>();

    // 5) output projection -> fp32 out
    gemm_f16<<<dim3(DIM / 128, S_TOT / 128), 256, SMEM_GEMM>>>(
        p_act, p_wp, proj_b, out, DIM);
}